// round 16
// baseline (speedup 1.0000x reference)
#include <cuda_runtime.h>
#include <cstdint>

// Problem constants
#define BATCH 2
#define NCAM  6
#define DD    48
#define HH    28
#define WW    60
#define CC    64
#define GX    128
#define GY    128
#define NTILES   1024            // BATCH * GY * (GX/32)
#define NUNITS   (NTILES * 16)   // x 16 channel groups
#define NBLOCKS  296             // 2 per SM, single wave
#define NWARPS   (NBLOCKS * 16)  // 4736

// ---------------------------------------------------------------------------
// Persistent single-wave kernel. Grid: 296 blocks x 512 threads (16 warps).
//
// Setup (once per block): warp 0, lanes 0..11 each compute one matrix
//   M = K @ inv(l2s)[0:3,:] (SIMT-redundant across lanes) -> sm_M[12*12].
//   One __syncthreads total; no other block-wide sync anywhere.
//
// Work unit U in [0,16384): tile = U>>4, cg = U&15.
//   tile -> b = tile>>9, y = (tile&511)>>2, bx = tile&3 (32-wide x tile).
//   Warp gwid handles U = gwid + k*4736. Consecutive warps share a tile
//   with consecutive cg -> frustum pixel records (256B) shared in cache.
//
// Per unit (warp-local, no sync):
//   lanes 0..23 run the exact divide-free interval test (R10-validated) for
//   combo = lane, reading M from sm_M; one ballot -> 24-bit mask.
//   If mask: iterate set bits ascending (deterministic FP order) — per-lane
//   projection + trilinear gather of channels 4cg..4cg+3. Coalesced stores.
// ---------------------------------------------------------------------------
__global__ void __launch_bounds__(512)
bev_kernel(const float* __restrict__ frustum,
           const float* __restrict__ intr,
           const float* __restrict__ l2s,
           float* __restrict__ out) {
    __shared__ float sm_M[BATCH * NCAM * 12];

    const int tid  = threadIdx.x;
    const int lane = tid & 31;
    const int wid  = tid >> 5;

    // ---- Setup: warp 0 computes all 12 matrices (lane = matrix index) ----
    if (tid < 32) {
        const int idxL = lane < 12 ? lane : 11;
        const float* m = l2s + idxL * 16;   // row-major 4x4
        const float* K = intr + idxL * 9;   // row-major 3x3

        float inv[16];
        inv[0]  =  m[5]*m[10]*m[15] - m[5]*m[11]*m[14] - m[9]*m[6]*m[15] + m[9]*m[7]*m[14] + m[13]*m[6]*m[11] - m[13]*m[7]*m[10];
        inv[4]  = -m[4]*m[10]*m[15] + m[4]*m[11]*m[14] + m[8]*m[6]*m[15] - m[8]*m[7]*m[14] - m[12]*m[6]*m[11] + m[12]*m[7]*m[10];
        inv[8]  =  m[4]*m[9]*m[15]  - m[4]*m[11]*m[13] - m[8]*m[5]*m[15] + m[8]*m[7]*m[13] + m[12]*m[5]*m[11] - m[12]*m[7]*m[9];
        inv[12] = -m[4]*m[9]*m[14]  + m[4]*m[10]*m[13] + m[8]*m[5]*m[14] - m[8]*m[6]*m[13] - m[12]*m[5]*m[10] + m[12]*m[6]*m[9];
        inv[1]  = -m[1]*m[10]*m[15] + m[1]*m[11]*m[14] + m[9]*m[2]*m[15] - m[9]*m[3]*m[14] - m[13]*m[2]*m[11] + m[13]*m[3]*m[10];
        inv[5]  =  m[0]*m[10]*m[15] - m[0]*m[11]*m[14] - m[8]*m[2]*m[15] + m[8]*m[3]*m[14] + m[12]*m[2]*m[11] - m[12]*m[3]*m[10];
        inv[9]  = -m[0]*m[9]*m[15]  + m[0]*m[11]*m[13] + m[8]*m[1]*m[15] - m[8]*m[3]*m[13] - m[12]*m[1]*m[11] + m[12]*m[3]*m[9];
        inv[13] =  m[0]*m[9]*m[14]  - m[0]*m[10]*m[13] - m[8]*m[1]*m[14] + m[8]*m[2]*m[13] + m[12]*m[1]*m[10] - m[12]*m[2]*m[9];
        inv[2]  =  m[1]*m[6]*m[15]  - m[1]*m[7]*m[14]  - m[5]*m[2]*m[15] + m[5]*m[3]*m[14] + m[13]*m[2]*m[7]  - m[13]*m[3]*m[6];
        inv[6]  = -m[0]*m[6]*m[15]  + m[0]*m[7]*m[14]  + m[4]*m[2]*m[15] - m[4]*m[3]*m[14] - m[12]*m[2]*m[7]  + m[12]*m[3]*m[6];
        inv[10] =  m[0]*m[5]*m[15]  - m[0]*m[7]*m[13]  - m[4]*m[1]*m[15] + m[4]*m[3]*m[13] + m[12]*m[1]*m[7]  - m[12]*m[3]*m[5];
        inv[14] = -m[0]*m[5]*m[14]  + m[0]*m[6]*m[13]  + m[4]*m[1]*m[14] - m[4]*m[2]*m[13] - m[12]*m[1]*m[6]  + m[12]*m[2]*m[5];
        inv[3]  = -m[1]*m[6]*m[11]  + m[1]*m[7]*m[10]  + m[5]*m[2]*m[11] - m[5]*m[3]*m[10] - m[9]*m[2]*m[7]   + m[9]*m[3]*m[6];
        inv[7]  =  m[0]*m[6]*m[11]  - m[0]*m[7]*m[10]  - m[4]*m[2]*m[11] + m[4]*m[3]*m[10] + m[8]*m[2]*m[7]   - m[8]*m[3]*m[6];
        inv[11] = -m[0]*m[5]*m[11]  + m[0]*m[7]*m[9]   + m[4]*m[1]*m[11] - m[4]*m[3]*m[9]  - m[8]*m[1]*m[7]   + m[8]*m[3]*m[5];
        inv[15] =  m[0]*m[5]*m[10]  - m[0]*m[6]*m[9]   - m[4]*m[1]*m[10] + m[4]*m[2]*m[9]  + m[8]*m[1]*m[6]   - m[8]*m[2]*m[5];

        float det = m[0]*inv[0] + m[1]*inv[4] + m[2]*inv[8] + m[3]*inv[12];
        float rdet = 1.0f / det;
        #pragma unroll
        for (int i = 0; i < 16; i++) inv[i] *= rdet;

        float Mr[12];
        #pragma unroll
        for (int r = 0; r < 3; r++) {
            #pragma unroll
            for (int c = 0; c < 4; c++) {
                Mr[r * 4 + c] = K[r*3 + 0] * inv[0*4 + c]
                              + K[r*3 + 1] * inv[1*4 + c]
                              + K[r*3 + 2] * inv[2*4 + c];
            }
        }
        if (lane < 12) {
            #pragma unroll
            for (int i = 0; i < 12; i++) sm_M[lane * 12 + i] = Mr[i];
        }
    }
    __syncthreads();

    const int gwid = blockIdx.x * 16 + wid;
    const float4* f4 = (const float4*)frustum;

    // ---- persistent unit loop: U = gwid, gwid + 4736, ... ----
    #pragma unroll 1
    for (int U = gwid; U < NUNITS; U += NWARPS) {
        const int tile = U >> 4;
        const int cg   = U & 15;          // channels 4cg..4cg+3
        const int b    = tile >> 9;       // tile / 512
        const int rem  = tile & 511;
        const int y    = rem >> 2;
        const int bx   = rem & 3;
        const int x0t  = bx * 32;

        const float gy = -47.625f + 0.75f * (float)y;

        // ---- warp-local exact interval test: lanes 0..23, combo = lane ----
        int pass = 0;
        if (lane < 24) {
            const int cam = lane >> 2;
            const int zz  = lane & 3;
            const float* Ms = &sm_M[(b * NCAM + cam) * 12];
            const float gz  = -3.0f + 2.0f * (float)zz;
            const float gxa = -47.625f + 0.75f * (float)(x0t);
            const float gxb = -47.625f + 0.75f * (float)(x0t + 31);
            const float DLO = 0.9770f;   // d > 2 - 48/47, widened down
            const float DHI = 51.05f;    // d < 2 + 48*48/47, widened up
            const float uc = Ms[1]*gy + Ms[2]*gz  + Ms[3];
            const float vc = Ms[5]*gy + Ms[6]*gz  + Ms[7];
            const float dc = Ms[9]*gy + Ms[10]*gz + Ms[11];
            float u0 = Ms[0]*gxa + uc, u1 = Ms[0]*gxb + uc;
            float v0 = Ms[4]*gxa + vc, v1 = Ms[4]*gxb + vc;
            float d0 = Ms[8]*gxa + dc, d1 = Ms[8]*gxb + dc;
            const float dmin = fminf(d0, d1), dmax = fmaxf(d0, d1);
            if (dmax > DLO && dmin < DHI) {
                if (dmin < DLO) {
                    // d crosses DLO inside tile; affine => exact crossing.
                    const float t  = (DLO - d0) / (d1 - d0);
                    const float uX = u0 + t * (u1 - u0);
                    const float vX = v0 + t * (v1 - v0);
                    if (d0 < DLO) { u0 = uX; v0 = vX; d0 = DLO; }
                    else          { u1 = uX; v1 = vX; d1 = DLO; }
                }
                // d > 0 on (sub)interval: multiply bounds through by d.
                const float sx = 59.0f / 60.0f, sy = 27.0f / 28.0f;
                const float a0 = sx * u0, a1 = sx * u1;
                const float e0 = sy * v0, e1 = sy * v1;
                const bool rej =
                    (fmaxf(a0 + 1.002f  * d0, a1 + 1.002f  * d1) <= 0.0f) ||
                    (fminf(a0 - 60.002f * d0, a1 - 60.002f * d1) >= 0.0f) ||
                    (fmaxf(e0 + 1.002f  * d0, e1 + 1.002f  * d1) <= 0.0f) ||
                    (fminf(e0 - 28.002f * d0, e1 - 28.002f * d1) >= 0.0f);
                pass = !rej;
            }
        }
        unsigned mk = __ballot_sync(0xffffffffu, pass);

        float a0 = 0.0f, a1 = 0.0f, a2 = 0.0f, a3 = 0.0f;

        if (mk) {
            const float gx = -47.625f + 0.75f * (float)(x0t + lane);
            // ---- gather-accumulate, ascending combos (deterministic) ----
            #pragma unroll 1
            while (mk) {
                const int combo = __ffs(mk) - 1;
                mk &= mk - 1;
                const int cam = combo >> 2;
                const int zz  = combo & 3;
                const float gz = -3.0f + 2.0f * (float)zz;
                const float* M = &sm_M[(b * NCAM + cam) * 12];
                const float u  = M[0]*gx + M[1]*gy + M[2]*gz  + M[3];
                const float v  = M[4]*gx + M[5]*gy + M[6]*gz  + M[7];
                const float d  = M[8]*gx + M[9]*gy + M[10]*gz + M[11];
                const float rd = 1.0f / d;
                const float ix = u * rd * (59.0f/60.0f);
                const float iy = v * rd * (27.0f/28.0f);
                const float iz = (d - 2.0f) * (47.0f/48.0f);
                const bool ok = (ix > -1.0f) && (ix < 60.0f)
                             && (iy > -1.0f) && (iy < 28.0f)
                             && (iz > -1.0f) && (iz < 48.0f);
                if (!ok) continue;

                const float fx0 = floorf(ix); const int ix0 = (int)fx0; const float fx = ix - fx0;
                const float fy0 = floorf(iy); const int iy0 = (int)fy0; const float fy = iy - fy0;
                const float fz0 = floorf(iz); const int iz0 = (int)fz0; const float fz = iz - fz0;

                const float wx0 = (ix0 >= 0)      ? (1.0f - fx) : 0.0f;
                const float wx1 = (ix0 <= WW - 2) ? fx          : 0.0f;
                const float wy0 = (iy0 >= 0)      ? (1.0f - fy) : 0.0f;
                const float wy1 = (iy0 <= HH - 2) ? fy          : 0.0f;
                const float wz0 = (iz0 >= 0)      ? (1.0f - fz) : 0.0f;
                const float wz1 = (iz0 <= DD - 2) ? fz          : 0.0f;

                const int base = (b * NCAM + cam) * (DD * HH * WW);  // pixels

                #pragma unroll
                for (int dz = 0; dz < 2; dz++) {
                    const float wz = dz ? wz1 : wz0;
                    if (wz == 0.0f) continue;
                    const int zoff = base + (iz0 + dz) * (HH * WW);
                    #pragma unroll
                    for (int dy = 0; dy < 2; dy++) {
                        const float wzy = wz * (dy ? wy1 : wy0);
                        if (wzy == 0.0f) continue;
                        const int yoff = zoff + (iy0 + dy) * WW;
                        #pragma unroll
                        for (int dx = 0; dx < 2; dx++) {
                            const float w = wzy * (dx ? wx1 : wx0);
                            if (w == 0.0f) continue;
                            const int pix = yoff + (ix0 + dx);
                            const float4 a = __ldg(f4 + (size_t)pix * (CC / 4) + cg);
                            a0 += w * a.x; a1 += w * a.y;
                            a2 += w * a.z; a3 += w * a.w;
                        }
                    }
                }
            }
        }

        // ---- coalesced stores: out[b][cg*4+j][y][x0t+lane] ----
        const int xg = x0t + lane;
        size_t obase = (((size_t)b * CC + cg * 4) * GY + y) * GX + xg;
        out[obase]                      = a0;
        out[obase + (size_t)(GY * GX)]  = a1;
        out[obase + (size_t)(2*GY*GX)]  = a2;
        out[obase + (size_t)(3*GY*GX)]  = a3;
    }
}

extern "C" void kernel_launch(void* const* d_in, const int* in_sizes, int n_in,
                              void* d_out, int out_size) {
    const float* frustum = (const float*)d_in[0];
    const float* intr    = (const float*)d_in[1];
    const float* l2s     = (const float*)d_in[2];
    float* out = (float*)d_out;

    bev_kernel<<<NBLOCKS, 512>>>(frustum, intr, l2s, out);
}

// round 17
// speedup vs baseline: 1.2267x; 1.2267x over previous
#include <cuda_runtime.h>
#include <cstdint>

// Problem constants
#define BATCH 2
#define NCAM  6
#define DD    48
#define HH    28
#define WW    60
#define CC    64
#define GX    128
#define GY    128
#define NTILES  1024             // BATCH * GY * 4
#define NBLOCKS 296
#define NWARPS  (NBLOCKS * 16)   // 4736
#define NUNITS  (NTILES * 128)   // tile x 8 x-octets x 16 channel groups
#define NTHREADS_TOT (NBLOCKS * 512)

__device__ float    g_M[BATCH * NCAM * 12];
__device__ unsigned g_mask[NTILES];

// ---------------------------------------------------------------------------
// Kernel 1 (prep): 16 blocks x 64 threads. Threads 0..11 of each block
// compute M = K @ inv(l2s)[0:3,:] into smem; then each thread runs the
// R10-validated exact divide-free interval test for its tile's 24 combos
// (serial scalar loop) -> g_mask[tile]. Block 0 also writes g_M.
// ---------------------------------------------------------------------------
__global__ void __launch_bounds__(64)
prep_kernel(const float* __restrict__ intr,
            const float* __restrict__ l2s) {
    __shared__ float sm_M[BATCH * NCAM * 12];
    const int tid = threadIdx.x;

    if (tid < 12) {
        const float* m = l2s + tid * 16;   // row-major 4x4
        const float* K = intr + tid * 9;   // row-major 3x3

        float inv[16];
        inv[0]  =  m[5]*m[10]*m[15] - m[5]*m[11]*m[14] - m[9]*m[6]*m[15] + m[9]*m[7]*m[14] + m[13]*m[6]*m[11] - m[13]*m[7]*m[10];
        inv[4]  = -m[4]*m[10]*m[15] + m[4]*m[11]*m[14] + m[8]*m[6]*m[15] - m[8]*m[7]*m[14] - m[12]*m[6]*m[11] + m[12]*m[7]*m[10];
        inv[8]  =  m[4]*m[9]*m[15]  - m[4]*m[11]*m[13] - m[8]*m[5]*m[15] + m[8]*m[7]*m[13] + m[12]*m[5]*m[11] - m[12]*m[7]*m[9];
        inv[12] = -m[4]*m[9]*m[14]  + m[4]*m[10]*m[13] + m[8]*m[5]*m[14] - m[8]*m[6]*m[13] - m[12]*m[5]*m[10] + m[12]*m[6]*m[9];
        inv[1]  = -m[1]*m[10]*m[15] + m[1]*m[11]*m[14] + m[9]*m[2]*m[15] - m[9]*m[3]*m[14] - m[13]*m[2]*m[11] + m[13]*m[3]*m[10];
        inv[5]  =  m[0]*m[10]*m[15] - m[0]*m[11]*m[14] - m[8]*m[2]*m[15] + m[8]*m[3]*m[14] + m[12]*m[2]*m[11] - m[12]*m[3]*m[10];
        inv[9]  = -m[0]*m[9]*m[15]  + m[0]*m[11]*m[13] + m[8]*m[1]*m[15] - m[8]*m[3]*m[13] - m[12]*m[1]*m[11] + m[12]*m[3]*m[9];
        inv[13] =  m[0]*m[9]*m[14]  - m[0]*m[10]*m[13] - m[8]*m[1]*m[14] + m[8]*m[2]*m[13] + m[12]*m[1]*m[10] - m[12]*m[2]*m[9];
        inv[2]  =  m[1]*m[6]*m[15]  - m[1]*m[7]*m[14]  - m[5]*m[2]*m[15] + m[5]*m[3]*m[14] + m[13]*m[2]*m[7]  - m[13]*m[3]*m[6];
        inv[6]  = -m[0]*m[6]*m[15]  + m[0]*m[7]*m[14]  + m[4]*m[2]*m[15] - m[4]*m[3]*m[14] - m[12]*m[2]*m[7]  + m[12]*m[3]*m[6];
        inv[10] =  m[0]*m[5]*m[15]  - m[0]*m[7]*m[13]  - m[4]*m[1]*m[15] + m[4]*m[3]*m[13] + m[12]*m[1]*m[7]  - m[12]*m[3]*m[5];
        inv[14] = -m[0]*m[5]*m[14]  + m[0]*m[6]*m[13]  + m[4]*m[1]*m[14] - m[4]*m[2]*m[13] - m[12]*m[1]*m[6]  + m[12]*m[2]*m[5];
        inv[3]  = -m[1]*m[6]*m[11]  + m[1]*m[7]*m[10]  + m[5]*m[2]*m[11] - m[5]*m[3]*m[10] - m[9]*m[2]*m[7]   + m[9]*m[3]*m[6];
        inv[7]  =  m[0]*m[6]*m[11]  - m[0]*m[7]*m[10]  - m[4]*m[2]*m[11] + m[4]*m[3]*m[10] + m[8]*m[2]*m[7]   - m[8]*m[3]*m[6];
        inv[11] = -m[0]*m[5]*m[11]  + m[0]*m[7]*m[9]   + m[4]*m[1]*m[11] - m[4]*m[3]*m[9]  - m[8]*m[1]*m[7]   + m[8]*m[3]*m[5];
        inv[15] =  m[0]*m[5]*m[10]  - m[0]*m[6]*m[9]   - m[4]*m[1]*m[10] + m[4]*m[2]*m[9]  + m[8]*m[1]*m[6]   - m[8]*m[2]*m[5];

        float det = m[0]*inv[0] + m[1]*inv[4] + m[2]*inv[8] + m[3]*inv[12];
        float rdet = 1.0f / det;
        #pragma unroll
        for (int i = 0; i < 16; i++) inv[i] *= rdet;

        #pragma unroll
        for (int r = 0; r < 3; r++) {
            #pragma unroll
            for (int c = 0; c < 4; c++) {
                float v = K[r*3 + 0] * inv[0*4 + c]
                        + K[r*3 + 1] * inv[1*4 + c]
                        + K[r*3 + 2] * inv[2*4 + c];
                sm_M[tid * 12 + r * 4 + c] = v;
                if (blockIdx.x == 0) g_M[tid * 12 + r * 4 + c] = v;
            }
        }
    }
    __syncthreads();

    // one tile per thread: exact interval test for each of 24 combos
    const int tile = blockIdx.x * 64 + tid;
    const int b    = tile >> 9;
    const int rem  = tile & 511;
    const int y    = rem >> 2;
    const int bx   = rem & 3;
    const float gy  = -47.625f + 0.75f * (float)y;
    const float gxa = -47.625f + 0.75f * (float)(bx * 32);
    const float gxb = gxa + 0.75f * 31.0f;
    const float DLO = 0.9770f;   // d > 2 - 48/47, widened down
    const float DHI = 51.05f;    // d < 2 + 48*48/47, widened up
    const float sx = 59.0f / 60.0f, sy = 27.0f / 28.0f;

    unsigned mask = 0;
    #pragma unroll 1
    for (int c = 0; c < 24; c++) {
        const int cam = c >> 2;
        const int zz  = c & 3;
        const float gz = -3.0f + 2.0f * (float)zz;
        const float* Ms = &sm_M[(b * NCAM + cam) * 12];
        const float uc = Ms[1]*gy + Ms[2]*gz  + Ms[3];
        const float vc = Ms[5]*gy + Ms[6]*gz  + Ms[7];
        const float dc = Ms[9]*gy + Ms[10]*gz + Ms[11];
        float u0 = Ms[0]*gxa + uc, u1 = Ms[0]*gxb + uc;
        float v0 = Ms[4]*gxa + vc, v1 = Ms[4]*gxb + vc;
        float d0 = Ms[8]*gxa + dc, d1 = Ms[8]*gxb + dc;
        const float dmin = fminf(d0, d1), dmax = fmaxf(d0, d1);
        int pass = 0;
        if (dmax > DLO && dmin < DHI) {
            if (dmin < DLO) {
                // d crosses DLO inside tile; affine => exact crossing.
                const float t  = (DLO - d0) / (d1 - d0);
                const float uX = u0 + t * (u1 - u0);
                const float vX = v0 + t * (v1 - v0);
                if (d0 < DLO) { u0 = uX; v0 = vX; d0 = DLO; }
                else          { u1 = uX; v1 = vX; d1 = DLO; }
            }
            const float a0 = sx * u0, a1 = sx * u1;
            const float e0 = sy * v0, e1 = sy * v1;
            const bool rej =
                (fmaxf(a0 + 1.002f  * d0, a1 + 1.002f  * d1) <= 0.0f) ||
                (fminf(a0 - 60.002f * d0, a1 - 60.002f * d1) >= 0.0f) ||
                (fmaxf(e0 + 1.002f  * d0, e1 + 1.002f  * d1) <= 0.0f) ||
                (fminf(e0 - 28.002f * d0, e1 - 28.002f * d1) >= 0.0f);
            pass = !rej;
        }
        mask |= (unsigned)pass << c;
    }
    g_mask[tile] = mask;
}

// ---------------------------------------------------------------------------
// Kernel 2 (main): 296 blocks x 512 threads, single wave.
// Phase A: zero-fill every output float4 whose tile mask is 0.
// Phase B: units u in [0, 131072): tile = u>>7, oct = (u>>4)&7, cg = u&15.
//   Skip if mask 0 (cached LDG). Active: lane = 4 x (xi) x 8 combo-slots;
//   each lane does the FULL projection + trilinear gather for ONE combo
//   (slot-th set bit; +8 strides if >8 combos) of its x, channels 4cg..4cg+3;
//   fixed shfl_xor butterfly (1,2,4) reduces the 8 slots; slot-0 lanes store.
//   Deterministic: mask-derived slot assignment + fixed reduction tree.
// ---------------------------------------------------------------------------
__global__ void __launch_bounds__(512)
main_kernel(const float* __restrict__ frustum, float* __restrict__ out) {
    __shared__ float sm_M[BATCH * NCAM * 12];
    const int tid = threadIdx.x;
    if (tid < BATCH * NCAM * 12) sm_M[tid] = g_M[tid];
    __syncthreads();

    // ---- Phase A: zero-fill inactive tiles' outputs (float4) ----
    {
        float4* o4 = (float4*)out;
        const int gtid = blockIdx.x * 512 + tid;
        const float4 z4 = make_float4(0.0f, 0.0f, 0.0f, 0.0f);
        #pragma unroll 1
        for (int i = gtid; i < (BATCH * CC * GY * GX) / 4; i += NTHREADS_TOT) {
            const int x4 = i & 31;
            const int y  = (i >> 5) & 127;
            const int b  = i >> 18;
            const int tile = (b * GY + y) * 4 + (x4 >> 3);
            if (__ldg(&g_mask[tile]) == 0u) o4[i] = z4;
        }
    }

    const int lane = tid & 31;
    const int wid  = tid >> 5;
    const int gwid = blockIdx.x * 16 + wid;
    const int xi   = lane >> 3;       // 0..3 : x within octet
    const int slot = lane & 7;        // 0..7 : combo slot
    const float4* f4 = (const float4*)frustum;

    // ---- Phase B: fine-grained gather units ----
    #pragma unroll 1
    for (int u = gwid; u < NUNITS; u += NWARPS) {
        const int tile = u >> 7;
        const unsigned mask = __ldg(&g_mask[tile]);
        if (!mask) continue;

        const int sub = u & 127;
        const int oct = sub >> 4;     // x-octet 0..7 (4 x each)
        const int cg  = sub & 15;     // channels 4cg..4cg+3
        const int b   = tile >> 9;
        const int rem = tile & 511;
        const int y   = rem >> 2;
        const int bx  = rem & 3;
        const int xg  = bx * 32 + oct * 4 + xi;

        const float gy = -47.625f + 0.75f * (float)y;
        const float gx = -47.625f + 0.75f * (float)xg;

        const int nc = __popc(mask);

        // strip slot lowest bits: mm's lowest set bit = slot-th combo
        unsigned mm = mask;
        #pragma unroll 1
        for (int s = 0; s < slot; s++) mm &= mm - 1;

        float a0 = 0.0f, a1 = 0.0f, a2 = 0.0f, a3 = 0.0f;

        #pragma unroll 1
        for (int k = slot; k < nc; k += 8) {
            const int combo = __ffs(mm) - 1;
            #pragma unroll
            for (int s = 0; s < 8; s++) mm &= mm - 1;   // advance 8 combos

            const int cam = combo >> 2;
            const int zz  = combo & 3;
            const float gz = -3.0f + 2.0f * (float)zz;
            const float* M = &sm_M[(b * NCAM + cam) * 12];
            const float u_  = M[0]*gx + M[1]*gy + M[2]*gz  + M[3];
            const float v_  = M[4]*gx + M[5]*gy + M[6]*gz  + M[7];
            const float d_  = M[8]*gx + M[9]*gy + M[10]*gz + M[11];
            const float rd  = 1.0f / d_;
            const float ix  = u_ * rd * (59.0f/60.0f);
            const float iy  = v_ * rd * (27.0f/28.0f);
            const float iz  = (d_ - 2.0f) * (47.0f/48.0f);
            const bool ok = (ix > -1.0f) && (ix < 60.0f)
                         && (iy > -1.0f) && (iy < 28.0f)
                         && (iz > -1.0f) && (iz < 48.0f);
            if (!ok) continue;

            const float fx0 = floorf(ix); const int ix0 = (int)fx0; const float fx = ix - fx0;
            const float fy0 = floorf(iy); const int iy0 = (int)fy0; const float fy = iy - fy0;
            const float fz0 = floorf(iz); const int iz0 = (int)fz0; const float fz = iz - fz0;

            const float wx0 = (ix0 >= 0)      ? (1.0f - fx) : 0.0f;
            const float wx1 = (ix0 <= WW - 2) ? fx          : 0.0f;
            const float wy0 = (iy0 >= 0)      ? (1.0f - fy) : 0.0f;
            const float wy1 = (iy0 <= HH - 2) ? fy          : 0.0f;
            const float wz0 = (iz0 >= 0)      ? (1.0f - fz) : 0.0f;
            const float wz1 = (iz0 <= DD - 2) ? fz          : 0.0f;

            const int base = (b * NCAM + cam) * (DD * HH * WW);   // pixels

            #pragma unroll
            for (int dz = 0; dz < 2; dz++) {
                const float wz = dz ? wz1 : wz0;
                if (wz == 0.0f) continue;
                const int zoff = base + (iz0 + dz) * (HH * WW);
                #pragma unroll
                for (int dy = 0; dy < 2; dy++) {
                    const float wzy = wz * (dy ? wy1 : wy0);
                    if (wzy == 0.0f) continue;
                    const int yoff = zoff + (iy0 + dy) * WW;
                    #pragma unroll
                    for (int dx = 0; dx < 2; dx++) {
                        const float w = wzy * (dx ? wx1 : wx0);
                        if (w == 0.0f) continue;
                        const int pix = yoff + (ix0 + dx);
                        const float4 a = __ldg(f4 + (size_t)pix * (CC / 4) + cg);
                        a0 += w * a.x; a1 += w * a.y;
                        a2 += w * a.z; a3 += w * a.w;
                    }
                }
            }
        }

        // ---- fixed butterfly over the 8 combo slots (deterministic) ----
        #pragma unroll
        for (int s = 1; s < 8; s <<= 1) {
            a0 += __shfl_xor_sync(0xffffffffu, a0, s);
            a1 += __shfl_xor_sync(0xffffffffu, a1, s);
            a2 += __shfl_xor_sync(0xffffffffu, a2, s);
            a3 += __shfl_xor_sync(0xffffffffu, a3, s);
        }

        if (slot == 0) {
            size_t obase = (((size_t)b * CC + cg * 4) * GY + y) * GX + xg;
            out[obase]                      = a0;
            out[obase + (size_t)(GY * GX)]  = a1;
            out[obase + (size_t)(2*GY*GX)]  = a2;
            out[obase + (size_t)(3*GY*GX)]  = a3;
        }
    }
}

extern "C" void kernel_launch(void* const* d_in, const int* in_sizes, int n_in,
                              void* d_out, int out_size) {
    const float* frustum = (const float*)d_in[0];
    const float* intr    = (const float*)d_in[1];
    const float* l2s     = (const float*)d_in[2];
    float* out = (float*)d_out;

    prep_kernel<<<16, 64>>>(intr, l2s);
    main_kernel<<<NBLOCKS, 512>>>(frustum, out);
}